// round 1
// baseline (speedup 1.0000x reference)
#include <cuda_runtime.h>
#include <math.h>

// Problem constants
#define Bc      8
#define Nc      1024
#define DIN     64
#define Hc      128
#define MSGc    128
#define Lc      5
#define TGTc    12
#define NLAYERS 3
#define BN      (Bc * Nc)          // 8192 nodes total

// ---------------- scratch (static device globals; no cudaMalloc allowed) ----
__device__ float d_h  [BN * Hc];            // current hidden state
__device__ float d_h0 [BN * Hc];            // padded initial state
__device__ float d_Ml [BN * Lc * MSGc];     // per-node per-label messages [node][l][o]
__device__ float d_agg[BN * MSGc];          // aggregated messages
__device__ float d_mask [BN];               // node_mask
__device__ float d_rmask[BN];               // read_mask
__device__ float d_partial[Bc * 16 * TGTc]; // readout partial sums

// ---------------------------------------------------------------- setup ----
__global__ void k_pad(const float* __restrict__ h_in) {
    int idx  = blockIdx.x * blockDim.x + threadIdx.x;  // over BN*128
    int d    = idx & 127;
    int node = idx >> 7;
    float v = (d < DIN) ? h_in[node * DIN + d] : 0.f;
    d_h0[idx] = v;
    d_h [idx] = v;
}

__global__ void k_mask(const float* __restrict__ h_in) {
    int warp = threadIdx.x >> 5, lane = threadIdx.x & 31;
    int node = blockIdx.x * 8 + warp;
    float v0 = h_in[node * DIN + lane];
    float v1 = h_in[node * DIN + 32 + lane];
    float sa = fabsf(v0) + fabsf(v1);
    float ss = v0 + v1;
    #pragma unroll
    for (int off = 16; off; off >>= 1) {
        sa += __shfl_xor_sync(0xffffffffu, sa, off);
        ss += __shfl_xor_sync(0xffffffffu, ss, off);
    }
    if (lane == 0) {
        d_mask [node] = (sa > 0.f) ? 1.f : 0.f;
        d_rmask[node] = (ss > 0.f) ? 1.f : 0.f;
    }
}

// --------------------------------------------- K1: Ml[node][l][:] = h@A_l ---
// grid (BN/32, L), 256 threads. 32-row tile of h staged in smem.
__global__ void k_msg(const float* __restrict__ A) {
    __shared__ float sh[32][128];
    int rt = blockIdx.x, l = blockIdx.y;
    int t = threadIdx.x;
    #pragma unroll
    for (int k = 0; k < 16; ++k) {
        int idx = t + k * 256;
        sh[idx >> 7][idx & 127] = d_h[rt * 32 * 128 + idx];
    }
    __syncthreads();
    int warp = t >> 5, lane = t & 31, j4 = lane * 4;

    float4 acc[4];
    #pragma unroll
    for (int r = 0; r < 4; ++r) acc[r] = make_float4(0.f, 0.f, 0.f, 0.f);

    const float* Ab = A + (size_t)l * 128 * 128 + j4;   // A[l][d][j4..]
    for (int d = 0; d < 128; ++d) {
        float4 a = *(const float4*)(Ab + (size_t)d * 128);
        #pragma unroll
        for (int r = 0; r < 4; ++r) {
            float hv = sh[warp + r * 8][d];
            acc[r].x += hv * a.x;
            acc[r].y += hv * a.y;
            acc[r].z += hv * a.z;
            acc[r].w += hv * a.w;
        }
    }
    #pragma unroll
    for (int r = 0; r < 4; ++r) {
        int node = rt * 32 + warp + r * 8;
        *(float4*)&d_Ml[((size_t)node * Lc + l) * MSGc + j4] = acc[r];
    }
}

// ------------------- K2: agg[b,v,:] = sum_w g[b,v,w] * Ml[e[b,v,w]][b,w,:] --
// grid (N/32, B), 256 threads. Per-edge: label-indexed LDG.128 (L1-resident),
// g/e as smem broadcasts. Warp = full o=128 (lane*4), 4 v-rows per warp.
__global__ void k_gather(const float* __restrict__ g, const int* __restrict__ e) {
    __shared__ float g_sm[32][64];
    __shared__ int   e_sm[32][64];
    int vt = blockIdx.x, b = blockIdx.y;
    int t = threadIdx.x, warp = t >> 5, lane = t & 31, j4 = lane * 4;
    int vbase = vt * 32;

    float4 acc[4];
    #pragma unroll
    for (int r = 0; r < 4; ++r) acc[r] = make_float4(0.f, 0.f, 0.f, 0.f);

    const float* Mlb = d_Ml + (size_t)b * Nc * Lc * MSGc + j4;

    for (int wt = 0; wt < 16; ++wt) {
        int wbase = wt * 64;
        __syncthreads();
        #pragma unroll
        for (int kk = 0; kk < 8; ++kk) {
            int idx = t + kk * 256;       // 2048 elements per array
            int r = idx >> 6, w = idx & 63;
            size_t gi = ((size_t)(b * Nc + vbase + r)) * Nc + wbase + w;
            g_sm[r][w] = g[gi];
            e_sm[r][w] = e[gi];
        }
        __syncthreads();

        int r0 = warp * 4;
        #pragma unroll 4
        for (int w = 0; w < 64; ++w) {
            const float* mb = Mlb + (size_t)(wbase + w) * (Lc * MSGc);
            #pragma unroll
            for (int r = 0; r < 4; ++r) {
                float c = g_sm[r0 + r][w];
                int   s = e_sm[r0 + r][w];
                float4 m = *(const float4*)(mb + s * MSGc);
                acc[r].x += c * m.x;
                acc[r].y += c * m.y;
                acc[r].z += c * m.z;
                acc[r].w += c * m.w;
            }
        }
    }
    int r0 = warp * 4;
    #pragma unroll
    for (int r = 0; r < 4; ++r) {
        int v = vbase + r0 + r;
        *(float4*)&d_agg[((size_t)(b * Nc + v)) * MSGc + j4] = acc[r];
    }
}

// -------------------------------------------------- K3: GRU step + mask -----
__device__ __forceinline__ float gru_comp(float irv, float izv, float inv,
                                          float hrv, float hzv, float hnv,
                                          float hold, float m) {
    float r = 1.f / (1.f + expf(-(irv + hrv)));
    float z = 1.f / (1.f + expf(-(izv + hzv)));
    float n = tanhf(inv + r * hnv);
    return ((1.f - z) * n + z * hold) * m;
}

// grid BN/8, 256 threads. Warp = one row; lane owns 4 consecutive j.
__global__ void k_gru(const float* __restrict__ Wi, const float* __restrict__ Wh,
                      const float* __restrict__ bi, const float* __restrict__ bh) {
    __shared__ float a_sm[8][128];
    __shared__ float h_sm[8][128];
    int tile = blockIdx.x;
    int t = threadIdx.x, warp = t >> 5, lane = t & 31, j4 = lane * 4;
    #pragma unroll
    for (int k = 0; k < 4; ++k) {
        int idx = t + k * 256;            // 1024 elements each
        a_sm[idx >> 7][idx & 127] = d_agg[(size_t)tile * 8 * 128 + idx];
        h_sm[idx >> 7][idx & 127] = d_h [(size_t)tile * 8 * 128 + idx];
    }
    __syncthreads();
    int row = tile * 8 + warp;

    float4 ir = *(const float4*)&bi[j4];
    float4 iz = *(const float4*)&bi[128 + j4];
    float4 in_ = *(const float4*)&bi[256 + j4];
    float4 hr = *(const float4*)&bh[j4];
    float4 hz = *(const float4*)&bh[128 + j4];
    float4 hn = *(const float4*)&bh[256 + j4];

    for (int d = 0; d < 128; ++d) {
        float av = a_sm[warp][d];
        float hv = h_sm[warp][d];
        const float* wi = Wi + (size_t)d * 384 + j4;
        const float* wh = Wh + (size_t)d * 384 + j4;
        float4 w0 = *(const float4*)(wi);
        float4 w1 = *(const float4*)(wi + 128);
        float4 w2 = *(const float4*)(wi + 256);
        float4 w3 = *(const float4*)(wh);
        float4 w4 = *(const float4*)(wh + 128);
        float4 w5 = *(const float4*)(wh + 256);
        ir.x += av * w0.x; ir.y += av * w0.y; ir.z += av * w0.z; ir.w += av * w0.w;
        iz.x += av * w1.x; iz.y += av * w1.y; iz.z += av * w1.z; iz.w += av * w1.w;
        in_.x += av * w2.x; in_.y += av * w2.y; in_.z += av * w2.z; in_.w += av * w2.w;
        hr.x += hv * w3.x; hr.y += hv * w3.y; hr.z += hv * w3.z; hr.w += hv * w3.w;
        hz.x += hv * w4.x; hz.y += hv * w4.y; hz.z += hv * w4.z; hz.w += hv * w4.w;
        hn.x += hv * w5.x; hn.y += hv * w5.y; hn.z += hv * w5.z; hn.w += hv * w5.w;
    }
    float m = d_mask[row];
    float4 out;
    out.x = gru_comp(ir.x, iz.x, in_.x, hr.x, hz.x, hn.x, h_sm[warp][j4 + 0], m);
    out.y = gru_comp(ir.y, iz.y, in_.y, hr.y, hz.y, hn.y, h_sm[warp][j4 + 1], m);
    out.z = gru_comp(ir.z, iz.z, in_.z, hr.z, hz.z, hn.z, h_sm[warp][j4 + 2], m);
    out.w = gru_comp(ir.w, iz.w, in_.w, hr.w, hz.w, hn.w, h_sm[warp][j4 + 3], m);
    *(float4*)&d_h[(size_t)row * 128 + j4] = out;
}

// ------------------------------------------------------------ readout ------
// grid (16, B), 256 threads. Thread = (node_local = t>>2, kgroup = t&3 -> 3 ks).
__global__ void k_readout(const float* __restrict__ Wg, const float* __restrict__ bg,
                          const float* __restrict__ Wo, const float* __restrict__ bo) {
    int tile = blockIdx.x, b = blockIdx.y;
    int t = threadIdx.x, lane = t & 31, warp = t >> 5;
    int nl = t >> 2;
    int kg = t & 3;
    int node = b * Nc + tile * 64 + nl;

    float acc_g[3], acc_o[3];
    #pragma unroll
    for (int k3 = 0; k3 < 3; ++k3) {
        int k = kg * 3 + k3;
        acc_g[k3] = bg[k];
        acc_o[k3] = bo[k];
    }
    const float* hT  = d_h  + (size_t)node * 128;
    const float* h0p = d_h0 + (size_t)node * 128;
    for (int d = 0; d < 128; ++d) {
        float ht  = hT[d];
        float h0v = h0p[d];
        #pragma unroll
        for (int k3 = 0; k3 < 3; ++k3) {
            int k = kg * 3 + k3;
            acc_g[k3] += ht * Wg[d * TGTc + k] + h0v * Wg[(128 + d) * TGTc + k];
            acc_o[k3] += ht * Wo[d * TGTc + k];
        }
    }
    float rm = d_rmask[node];
    float vals[3];
    #pragma unroll
    for (int k3 = 0; k3 < 3; ++k3) {
        float gate = 1.f / (1.f + expf(-acc_g[k3]));
        vals[k3] = rm * gate * acc_o[k3];
    }
    // reduce over 8 nodes per warp; xor 16/8/4 preserves lane%4 (= kgroup)
    #pragma unroll
    for (int off = 16; off >= 4; off >>= 1) {
        #pragma unroll
        for (int k3 = 0; k3 < 3; ++k3)
            vals[k3] += __shfl_xor_sync(0xffffffffu, vals[k3], off);
    }
    __shared__ float red[8][TGTc];
    if (lane < 4) {
        #pragma unroll
        for (int k3 = 0; k3 < 3; ++k3) red[warp][lane * 3 + k3] = vals[k3];
    }
    __syncthreads();
    if (t < TGTc) {
        float s = 0.f;
        #pragma unroll
        for (int wq = 0; wq < 8; ++wq) s += red[wq][t];
        d_partial[(b * 16 + tile) * TGTc + t] = s;
    }
}

__global__ void k_final(float* __restrict__ out) {
    int t = threadIdx.x;
    if (t < Bc * TGTc) {
        int b = t / TGTc, k = t % TGTc;
        float s = 0.f;
        #pragma unroll
        for (int i = 0; i < 16; ++i) s += d_partial[(b * 16 + i) * TGTc + k];
        out[t] = s;
    }
}

// ---------------------------------------------------------------------------
extern "C" void kernel_launch(void* const* d_in, const int* in_sizes, int n_in,
                              void* d_out, int out_size) {
    const float* g    = (const float*)d_in[0];
    const float* h_in = (const float*)d_in[1];
    const int*   e    = (const int*)  d_in[2];
    const float* A    = (const float*)d_in[3];
    const float* Wi   = (const float*)d_in[4];
    const float* Wh   = (const float*)d_in[5];
    const float* bi   = (const float*)d_in[6];
    const float* bh   = (const float*)d_in[7];
    const float* Wg   = (const float*)d_in[8];
    const float* bg   = (const float*)d_in[9];
    const float* Wo   = (const float*)d_in[10];
    const float* bo   = (const float*)d_in[11];
    float* out = (float*)d_out;

    k_pad <<<BN * Hc / 256, 256>>>(h_in);
    k_mask<<<BN / 8, 256>>>(h_in);

    for (int layer = 0; layer < NLAYERS; ++layer) {
        k_msg   <<<dim3(BN / 32, Lc), 256>>>(A);
        k_gather<<<dim3(Nc / 32, Bc), 256>>>(g, e);
        k_gru   <<<BN / 8, 256>>>(Wi, Wh, bi, bh);
    }

    k_readout<<<dim3(16, Bc), 256>>>(Wg, bg, Wo, bo);
    k_final  <<<1, 128>>>(out);
}

// round 2
// speedup vs baseline: 1.0029x; 1.0029x over previous
#include <cuda_runtime.h>
#include <math.h>

// Problem constants
#define Bc      8
#define Nc      1024
#define DIN     64
#define Hc      128
#define MSGc    128
#define Lc      5
#define TGTc    12
#define NLAYERS 3
#define BN      (Bc * Nc)          // 8192 nodes total

// ---------------- scratch (static device globals; no cudaMalloc allowed) ----
__device__ float d_h  [BN * Hc];            // current hidden state
__device__ float d_h0 [BN * Hc];            // padded initial state
__device__ float d_Ml [BN * Lc * MSGc];     // per-node per-label messages [node][l][o]
__device__ float d_agg[BN * MSGc];          // aggregated messages
__device__ float d_mask [BN];               // node_mask
__device__ float d_rmask[BN];               // read_mask
__device__ float d_partial[Bc * 16 * TGTc]; // readout partial sums

// ---------------------------------------------------------------- setup ----
__global__ void k_pad(const float* __restrict__ h_in) {
    int idx  = blockIdx.x * blockDim.x + threadIdx.x;  // over BN*128
    int d    = idx & 127;
    int node = idx >> 7;
    float v = (d < DIN) ? h_in[node * DIN + d] : 0.f;
    d_h0[idx] = v;
    d_h [idx] = v;
}

__global__ void k_mask(const float* __restrict__ h_in) {
    int warp = threadIdx.x >> 5, lane = threadIdx.x & 31;
    int node = blockIdx.x * 8 + warp;
    float v0 = h_in[node * DIN + lane];
    float v1 = h_in[node * DIN + 32 + lane];
    float sa = fabsf(v0) + fabsf(v1);
    float ss = v0 + v1;
    #pragma unroll
    for (int off = 16; off; off >>= 1) {
        sa += __shfl_xor_sync(0xffffffffu, sa, off);
        ss += __shfl_xor_sync(0xffffffffu, ss, off);
    }
    if (lane == 0) {
        d_mask [node] = (sa > 0.f) ? 1.f : 0.f;
        d_rmask[node] = (ss > 0.f) ? 1.f : 0.f;
    }
}

// --------------------------------------------- K1: Ml[node][l][:] = h@A_l ---
// grid (BN/32, L), 256 threads. 32-row tile of h staged in smem.
__global__ void k_msg(const float* __restrict__ A) {
    __shared__ float sh[32][128];
    int rt = blockIdx.x, l = blockIdx.y;
    int t = threadIdx.x;
    #pragma unroll
    for (int k = 0; k < 16; ++k) {
        int idx = t + k * 256;
        sh[idx >> 7][idx & 127] = d_h[rt * 32 * 128 + idx];
    }
    __syncthreads();
    int warp = t >> 5, lane = t & 31, j4 = lane * 4;

    float4 acc[4];
    #pragma unroll
    for (int r = 0; r < 4; ++r) acc[r] = make_float4(0.f, 0.f, 0.f, 0.f);

    const float* Ab = A + (size_t)l * 128 * 128 + j4;   // A[l][d][j4..]
    for (int d = 0; d < 128; ++d) {
        float4 a = *(const float4*)(Ab + (size_t)d * 128);
        #pragma unroll
        for (int r = 0; r < 4; ++r) {
            float hv = sh[warp + r * 8][d];
            acc[r].x += hv * a.x;
            acc[r].y += hv * a.y;
            acc[r].z += hv * a.z;
            acc[r].w += hv * a.w;
        }
    }
    #pragma unroll
    for (int r = 0; r < 4; ++r) {
        int node = rt * 32 + warp + r * 8;
        *(float4*)&d_Ml[((size_t)node * Lc + l) * MSGc + j4] = acc[r];
    }
}

// ------------------- K2: agg[b,v,:] = sum_w g[b,v,w] * Ml[e[b,v,w]][b,w,:] --
// grid (N/32, B), 256 threads. Per-edge: label-indexed LDG.128 (L1-resident),
// g/e as smem broadcasts. Warp = full o=128 (lane*4), 4 v-rows per warp.
__global__ void k_gather(const float* __restrict__ g, const int* __restrict__ e) {
    __shared__ float g_sm[32][64];
    __shared__ int   e_sm[32][64];
    int vt = blockIdx.x, b = blockIdx.y;
    int t = threadIdx.x, warp = t >> 5, lane = t & 31, j4 = lane * 4;
    int vbase = vt * 32;

    float4 acc[4];
    #pragma unroll
    for (int r = 0; r < 4; ++r) acc[r] = make_float4(0.f, 0.f, 0.f, 0.f);

    const float* Mlb = d_Ml + (size_t)b * Nc * Lc * MSGc + j4;

    for (int wt = 0; wt < 16; ++wt) {
        int wbase = wt * 64;
        __syncthreads();
        #pragma unroll
        for (int kk = 0; kk < 8; ++kk) {
            int idx = t + kk * 256;       // 2048 elements per array
            int r = idx >> 6, w = idx & 63;
            size_t gi = ((size_t)(b * Nc + vbase + r)) * Nc + wbase + w;
            g_sm[r][w] = g[gi];
            e_sm[r][w] = e[gi];
        }
        __syncthreads();

        int r0 = warp * 4;
        #pragma unroll 4
        for (int w = 0; w < 64; ++w) {
            const float* mb = Mlb + (size_t)(wbase + w) * (Lc * MSGc);
            #pragma unroll
            for (int r = 0; r < 4; ++r) {
                float c = g_sm[r0 + r][w];
                int   s = e_sm[r0 + r][w];
                float4 m = *(const float4*)(mb + s * MSGc);
                acc[r].x += c * m.x;
                acc[r].y += c * m.y;
                acc[r].z += c * m.z;
                acc[r].w += c * m.w;
            }
        }
    }
    int r0 = warp * 4;
    #pragma unroll
    for (int r = 0; r < 4; ++r) {
        int v = vbase + r0 + r;
        *(float4*)&d_agg[((size_t)(b * Nc + v)) * MSGc + j4] = acc[r];
    }
}

// -------------------------------------------------- K3: GRU step + mask -----
__device__ __forceinline__ float gru_comp(float irv, float izv, float inv,
                                          float hrv, float hzv, float hnv,
                                          float hold, float m) {
    float r = 1.f / (1.f + expf(-(irv + hrv)));
    float z = 1.f / (1.f + expf(-(izv + hzv)));
    float n = tanhf(inv + r * hnv);
    return ((1.f - z) * n + z * hold) * m;
}

// grid BN/8, 256 threads. Warp = one row; lane owns 4 consecutive j.
__global__ void k_gru(const float* __restrict__ Wi, const float* __restrict__ Wh,
                      const float* __restrict__ bi, const float* __restrict__ bh) {
    __shared__ float a_sm[8][128];
    __shared__ float h_sm[8][128];
    int tile = blockIdx.x;
    int t = threadIdx.x, warp = t >> 5, lane = t & 31, j4 = lane * 4;
    #pragma unroll
    for (int k = 0; k < 4; ++k) {
        int idx = t + k * 256;            // 1024 elements each
        a_sm[idx >> 7][idx & 127] = d_agg[(size_t)tile * 8 * 128 + idx];
        h_sm[idx >> 7][idx & 127] = d_h [(size_t)tile * 8 * 128 + idx];
    }
    __syncthreads();
    int row = tile * 8 + warp;

    float4 ir = *(const float4*)&bi[j4];
    float4 iz = *(const float4*)&bi[128 + j4];
    float4 in_ = *(const float4*)&bi[256 + j4];
    float4 hr = *(const float4*)&bh[j4];
    float4 hz = *(const float4*)&bh[128 + j4];
    float4 hn = *(const float4*)&bh[256 + j4];

    for (int d = 0; d < 128; ++d) {
        float av = a_sm[warp][d];
        float hv = h_sm[warp][d];
        const float* wi = Wi + (size_t)d * 384 + j4;
        const float* wh = Wh + (size_t)d * 384 + j4;
        float4 w0 = *(const float4*)(wi);
        float4 w1 = *(const float4*)(wi + 128);
        float4 w2 = *(const float4*)(wi + 256);
        float4 w3 = *(const float4*)(wh);
        float4 w4 = *(const float4*)(wh + 128);
        float4 w5 = *(const float4*)(wh + 256);
        ir.x += av * w0.x; ir.y += av * w0.y; ir.z += av * w0.z; ir.w += av * w0.w;
        iz.x += av * w1.x; iz.y += av * w1.y; iz.z += av * w1.z; iz.w += av * w1.w;
        in_.x += av * w2.x; in_.y += av * w2.y; in_.z += av * w2.z; in_.w += av * w2.w;
        hr.x += hv * w3.x; hr.y += hv * w3.y; hr.z += hv * w3.z; hr.w += hv * w3.w;
        hz.x += hv * w4.x; hz.y += hv * w4.y; hz.z += hv * w4.z; hz.w += hv * w4.w;
        hn.x += hv * w5.x; hn.y += hv * w5.y; hn.z += hv * w5.z; hn.w += hv * w5.w;
    }
    float m = d_mask[row];
    float4 out;
    out.x = gru_comp(ir.x, iz.x, in_.x, hr.x, hz.x, hn.x, h_sm[warp][j4 + 0], m);
    out.y = gru_comp(ir.y, iz.y, in_.y, hr.y, hz.y, hn.y, h_sm[warp][j4 + 1], m);
    out.z = gru_comp(ir.z, iz.z, in_.z, hr.z, hz.z, hn.z, h_sm[warp][j4 + 2], m);
    out.w = gru_comp(ir.w, iz.w, in_.w, hr.w, hz.w, hn.w, h_sm[warp][j4 + 3], m);
    *(float4*)&d_h[(size_t)row * 128 + j4] = out;
}

// ------------------------------------------------------------ readout ------
// grid (16, B), 256 threads. Thread = (node_local = t>>2, kgroup = t&3 -> 3 ks).
__global__ void k_readout(const float* __restrict__ Wg, const float* __restrict__ bg,
                          const float* __restrict__ Wo, const float* __restrict__ bo) {
    int tile = blockIdx.x, b = blockIdx.y;
    int t = threadIdx.x, lane = t & 31, warp = t >> 5;
    int nl = t >> 2;
    int kg = t & 3;
    int node = b * Nc + tile * 64 + nl;

    float acc_g[3], acc_o[3];
    #pragma unroll
    for (int k3 = 0; k3 < 3; ++k3) {
        int k = kg * 3 + k3;
        acc_g[k3] = bg[k];
        acc_o[k3] = bo[k];
    }
    const float* hT  = d_h  + (size_t)node * 128;
    const float* h0p = d_h0 + (size_t)node * 128;
    for (int d = 0; d < 128; ++d) {
        float ht  = hT[d];
        float h0v = h0p[d];
        #pragma unroll
        for (int k3 = 0; k3 < 3; ++k3) {
            int k = kg * 3 + k3;
            acc_g[k3] += ht * Wg[d * TGTc + k] + h0v * Wg[(128 + d) * TGTc + k];
            acc_o[k3] += ht * Wo[d * TGTc + k];
        }
    }
    float rm = d_rmask[node];
    float vals[3];
    #pragma unroll
    for (int k3 = 0; k3 < 3; ++k3) {
        float gate = 1.f / (1.f + expf(-acc_g[k3]));
        vals[k3] = rm * gate * acc_o[k3];
    }
    // reduce over 8 nodes per warp; xor 16/8/4 preserves lane%4 (= kgroup)
    #pragma unroll
    for (int off = 16; off >= 4; off >>= 1) {
        #pragma unroll
        for (int k3 = 0; k3 < 3; ++k3)
            vals[k3] += __shfl_xor_sync(0xffffffffu, vals[k3], off);
    }
    __shared__ float red[8][TGTc];
    if (lane < 4) {
        #pragma unroll
        for (int k3 = 0; k3 < 3; ++k3) red[warp][lane * 3 + k3] = vals[k3];
    }
    __syncthreads();
    if (t < TGTc) {
        float s = 0.f;
        #pragma unroll
        for (int wq = 0; wq < 8; ++wq) s += red[wq][t];
        d_partial[(b * 16 + tile) * TGTc + t] = s;
    }
}

__global__ void k_final(float* __restrict__ out) {
    int t = threadIdx.x;
    if (t < Bc * TGTc) {
        int b = t / TGTc, k = t % TGTc;
        float s = 0.f;
        #pragma unroll
        for (int i = 0; i < 16; ++i) s += d_partial[(b * 16 + i) * TGTc + k];
        out[t] = s;
    }
}

// ---------------------------------------------------------------------------
extern "C" void kernel_launch(void* const* d_in, const int* in_sizes, int n_in,
                              void* d_out, int out_size) {
    const float* g    = (const float*)d_in[0];
    const float* h_in = (const float*)d_in[1];
    const int*   e    = (const int*)  d_in[2];
    const float* A    = (const float*)d_in[3];
    const float* Wi   = (const float*)d_in[4];
    const float* Wh   = (const float*)d_in[5];
    const float* bi   = (const float*)d_in[6];
    const float* bh   = (const float*)d_in[7];
    const float* Wg   = (const float*)d_in[8];
    const float* bg   = (const float*)d_in[9];
    const float* Wo   = (const float*)d_in[10];
    const float* bo   = (const float*)d_in[11];
    float* out = (float*)d_out;

    k_pad <<<BN * Hc / 256, 256>>>(h_in);
    k_mask<<<BN / 8, 256>>>(h_in);

    for (int layer = 0; layer < NLAYERS; ++layer) {
        k_msg   <<<dim3(BN / 32, Lc), 256>>>(A);
        k_gather<<<dim3(Nc / 32, Bc), 256>>>(g, e);
        k_gru   <<<BN / 8, 256>>>(Wi, Wh, bi, bh);
    }

    k_readout<<<dim3(16, Bc), 256>>>(Wg, bg, Wo, bo);
    k_final  <<<1, 128>>>(out);
}

// round 3
// speedup vs baseline: 1.3986x; 1.3946x over previous
#include <cuda_runtime.h>
#include <math.h>

// Problem constants
#define Bc      8
#define Nc      1024
#define DIN     64
#define Hc      128
#define MSGc    128
#define Lc      5
#define TGTc    12
#define NLAYERS 3
#define BN      (Bc * Nc)          // 8192 nodes total
#define SPLIT   4                  // w-dimension split for gather

// ---------------- scratch (static device globals; no cudaMalloc allowed) ----
__device__ float d_h  [BN * Hc];
__device__ float d_h0 [BN * Hc];
__device__ float d_Ml [BN * Lc * MSGc];       // [b][w][l][o]
__device__ float d_aggp[SPLIT][BN * MSGc];    // partial aggregates per w-split
__device__ float d_mask [BN];
__device__ float d_rmask[BN];
__device__ float d_partial[Bc * 16 * TGTc];
__device__ uint2 d_packbuf[(size_t)BN * Nc];  // {g bits, element offset (w*5+e)*128}

__device__ __forceinline__ void fma4(float4& a, float s, const float4& w) {
    a.x += s * w.x; a.y += s * w.y; a.z += s * w.z; a.w += s * w.w;
}

// ---------------------------------------------------------------- setup ----
__global__ void k_pad(const float* __restrict__ h_in) {
    int idx  = blockIdx.x * blockDim.x + threadIdx.x;
    int d    = idx & 127;
    int node = idx >> 7;
    float v = (d < DIN) ? h_in[node * DIN + d] : 0.f;
    d_h0[idx] = v;
    d_h [idx] = v;
}

__global__ void k_mask(const float* __restrict__ h_in) {
    int warp = threadIdx.x >> 5, lane = threadIdx.x & 31;
    int node = blockIdx.x * 8 + warp;
    float v0 = h_in[node * DIN + lane];
    float v1 = h_in[node * DIN + 32 + lane];
    float sa = fabsf(v0) + fabsf(v1);
    float ss = v0 + v1;
    #pragma unroll
    for (int off = 16; off; off >>= 1) {
        sa += __shfl_xor_sync(0xffffffffu, sa, off);
        ss += __shfl_xor_sync(0xffffffffu, ss, off);
    }
    if (lane == 0) {
        d_mask [node] = (sa > 0.f) ? 1.f : 0.f;
        d_rmask[node] = (ss > 0.f) ? 1.f : 0.f;
    }
}

// Precompute fused coefficient+offset array (reused by all 3 layers).
__global__ void k_pack(const float* __restrict__ g, const int* __restrict__ e) {
    size_t i = (size_t)blockIdx.x * blockDim.x + threadIdx.x;   // over BN*Nc
    int w = (int)(i & (Nc - 1));
    int s = e[i];
    uint2 p;
    p.x = __float_as_uint(g[i]);
    p.y = (unsigned)((w * Lc + s) * MSGc);
    d_packbuf[i] = p;
}

// --------------------------------------------- K1: Ml[node][l][:] = h@A_l ---
__global__ void k_msg(const float* __restrict__ A) {
    __shared__ float sh[32][128];
    int rt = blockIdx.x, l = blockIdx.y;
    int t = threadIdx.x;
    #pragma unroll
    for (int k = 0; k < 16; ++k) {
        int idx = t + k * 256;
        sh[idx >> 7][idx & 127] = d_h[(size_t)rt * 32 * 128 + idx];
    }
    __syncthreads();
    int warp = t >> 5, lane = t & 31, j4 = lane * 4;

    float4 acc[4];
    #pragma unroll
    for (int r = 0; r < 4; ++r) acc[r] = make_float4(0.f, 0.f, 0.f, 0.f);

    const float* Ab = A + (size_t)l * 128 * 128 + j4;
    for (int d = 0; d < 128; ++d) {
        float4 a = *(const float4*)(Ab + (size_t)d * 128);
        #pragma unroll
        for (int r = 0; r < 4; ++r) fma4(acc[r], sh[warp + r * 8][d], a);
    }
    #pragma unroll
    for (int r = 0; r < 4; ++r) {
        int node = rt * 32 + warp + r * 8;
        *(float4*)&d_Ml[((size_t)node * Lc + l) * MSGc + j4] = acc[r];
    }
}

// ------------------- K2: aggp[sp][b,v,:] = sum_{w in split} g*Ml[e][w,:] ----
// grid (N/32, B, SPLIT), 256 threads. Coefficient+offset via one LDS.64
// broadcast; message row via label-indexed LDG.128 (L1-resident).
__global__ void __launch_bounds__(256, 4)
k_gather() {
    __shared__ uint2 p_sm[32][64];      // 16 KB
    int vt = blockIdx.x, b = blockIdx.y, sp = blockIdx.z;
    int t = threadIdx.x, warp = t >> 5, lane = t & 31, j4 = lane * 4;
    int vbase = vt * 32;

    float4 acc[4];
    #pragma unroll
    for (int r = 0; r < 4; ++r) acc[r] = make_float4(0.f, 0.f, 0.f, 0.f);

    const float* Mlb = d_Ml + (size_t)b * Nc * Lc * MSGc + j4;

    for (int wt = sp * 4; wt < sp * 4 + 4; ++wt) {
        int wbase = wt * 64;
        __syncthreads();
        #pragma unroll
        for (int kk = 0; kk < 8; ++kk) {
            int idx = t + kk * 256;
            int r = idx >> 6, w = idx & 63;
            p_sm[r][w] = d_packbuf[((size_t)(b * Nc + vbase + r)) * Nc + wbase + w];
        }
        __syncthreads();

        int r0 = warp * 4;
        #pragma unroll 4
        for (int w = 0; w < 64; ++w) {
            #pragma unroll
            for (int r = 0; r < 4; ++r) {
                uint2 pk = p_sm[r0 + r][w];
                float c = __uint_as_float(pk.x);
                float4 m = *(const float4*)(Mlb + pk.y);
                fma4(acc[r], c, m);
            }
        }
    }
    int r0 = warp * 4;
    #pragma unroll
    for (int r = 0; r < 4; ++r) {
        int v = vbase + r0 + r;
        *(float4*)&d_aggp[sp][((size_t)(b * Nc + v)) * MSGc + j4] = acc[r];
    }
}

// -------------------------------------------------- K3: GRU step + mask -----
// Warp-pair design: even warp computes gi = (sum of agg partials)@Wi + bi for
// 4 rows; odd warp computes gh = h@Wh + bh for the SAME 4 rows. Weight float4s
// loaded once per d and reused across 4 rows (4x fewer weight wavefronts).
__device__ __forceinline__ float gru_comp(float irv, float izv, float inv,
                                          float hrv, float hzv, float hnv,
                                          float hold, float m) {
    float r = 1.f / (1.f + expf(-(irv + hrv)));
    float z = 1.f / (1.f + expf(-(izv + hzv)));
    float n = tanhf(inv + r * hnv);
    return ((1.f - z) * n + z * hold) * m;
}

__global__ void k_gru(const float* __restrict__ Wi, const float* __restrict__ Wh,
                      const float* __restrict__ bi, const float* __restrict__ bh) {
    __shared__ float a_sm[16][128];      // 8 KB   summed agg
    __shared__ float h_sm[16][128];      // 8 KB
    __shared__ float gh_sm[16][384];     // 24 KB  odd-warp results
    int tile = blockIdx.x;               // 512 blocks, 16 rows each
    int t = threadIdx.x, warp = t >> 5, lane = t & 31, j4 = lane * 4;
    int pair = warp >> 1;
    bool isI = (warp & 1) == 0;
    int rbase = pair * 4;

    #pragma unroll
    for (int k = 0; k < 8; ++k) {
        int idx = t + k * 256;                   // 2048 elements
        size_t go = (size_t)tile * 16 * 128 + idx;
        a_sm[idx >> 7][idx & 127] = d_aggp[0][go] + d_aggp[1][go]
                                  + d_aggp[2][go] + d_aggp[3][go];
        h_sm[idx >> 7][idx & 127] = d_h[go];
    }
    __syncthreads();

    const float* W  = isI ? Wi : Wh;
    const float* bb = isI ? bi : bh;
    float (*src)[128] = isI ? a_sm : h_sm;

    float4 acc[4][3];
    #pragma unroll
    for (int r = 0; r < 4; ++r)
        #pragma unroll
        for (int gq = 0; gq < 3; ++gq)
            acc[r][gq] = *(const float4*)&bb[gq * 128 + j4];

    for (int d = 0; d < 128; ++d) {
        const float* wrow = W + (size_t)d * 384 + j4;
        float4 w0 = *(const float4*)(wrow);
        float4 w1 = *(const float4*)(wrow + 128);
        float4 w2 = *(const float4*)(wrow + 256);
        #pragma unroll
        for (int r = 0; r < 4; ++r) {
            float v = src[rbase + r][d];
            fma4(acc[r][0], v, w0);
            fma4(acc[r][1], v, w1);
            fma4(acc[r][2], v, w2);
        }
    }

    if (!isI) {
        #pragma unroll
        for (int r = 0; r < 4; ++r)
            #pragma unroll
            for (int gq = 0; gq < 3; ++gq)
                *(float4*)&gh_sm[rbase + r][gq * 128 + j4] = acc[r][gq];
    }
    __syncthreads();
    if (isI) {
        #pragma unroll
        for (int r = 0; r < 4; ++r) {
            int row = tile * 16 + rbase + r;
            float m = d_mask[row];
            float4 hr = *(const float4*)&gh_sm[rbase + r][j4];
            float4 hz = *(const float4*)&gh_sm[rbase + r][128 + j4];
            float4 hn = *(const float4*)&gh_sm[rbase + r][256 + j4];
            float4 hold = *(const float4*)&h_sm[rbase + r][j4];
            float4 out;
            out.x = gru_comp(acc[r][0].x, acc[r][1].x, acc[r][2].x, hr.x, hz.x, hn.x, hold.x, m);
            out.y = gru_comp(acc[r][0].y, acc[r][1].y, acc[r][2].y, hr.y, hz.y, hn.y, hold.y, m);
            out.z = gru_comp(acc[r][0].z, acc[r][1].z, acc[r][2].z, hr.z, hz.z, hn.z, hold.z, m);
            out.w = gru_comp(acc[r][0].w, acc[r][1].w, acc[r][2].w, hr.w, hz.w, hn.w, hold.w, m);
            *(float4*)&d_h[(size_t)row * 128 + j4] = out;
        }
    }
}

// ------------------------------------------------------------ readout ------
__global__ void k_readout(const float* __restrict__ Wg, const float* __restrict__ bg,
                          const float* __restrict__ Wo, const float* __restrict__ bo) {
    int tile = blockIdx.x, b = blockIdx.y;
    int t = threadIdx.x, lane = t & 31, warp = t >> 5;
    int nl = t >> 2;
    int kg = t & 3;
    int node = b * Nc + tile * 64 + nl;

    float acc_g[3], acc_o[3];
    #pragma unroll
    for (int k3 = 0; k3 < 3; ++k3) {
        int k = kg * 3 + k3;
        acc_g[k3] = bg[k];
        acc_o[k3] = bo[k];
    }
    const float* hT  = d_h  + (size_t)node * 128;
    const float* h0p = d_h0 + (size_t)node * 128;
    for (int d = 0; d < 128; ++d) {
        float ht  = hT[d];
        float h0v = h0p[d];
        #pragma unroll
        for (int k3 = 0; k3 < 3; ++k3) {
            int k = kg * 3 + k3;
            acc_g[k3] += ht * Wg[d * TGTc + k] + h0v * Wg[(128 + d) * TGTc + k];
            acc_o[k3] += ht * Wo[d * TGTc + k];
        }
    }
    float rm = d_rmask[node];
    float vals[3];
    #pragma unroll
    for (int k3 = 0; k3 < 3; ++k3) {
        float gate = 1.f / (1.f + expf(-acc_g[k3]));
        vals[k3] = rm * gate * acc_o[k3];
    }
    #pragma unroll
    for (int off = 16; off >= 4; off >>= 1) {
        #pragma unroll
        for (int k3 = 0; k3 < 3; ++k3)
            vals[k3] += __shfl_xor_sync(0xffffffffu, vals[k3], off);
    }
    __shared__ float red[8][TGTc];
    if (lane < 4) {
        #pragma unroll
        for (int k3 = 0; k3 < 3; ++k3) red[warp][lane * 3 + k3] = vals[k3];
    }
    __syncthreads();
    if (t < TGTc) {
        float s = 0.f;
        #pragma unroll
        for (int wq = 0; wq < 8; ++wq) s += red[wq][t];
        d_partial[(b * 16 + tile) * TGTc + t] = s;
    }
}

__global__ void k_final(float* __restrict__ out) {
    int t = threadIdx.x;
    if (t < Bc * TGTc) {
        int b = t / TGTc, k = t % TGTc;
        float s = 0.f;
        #pragma unroll
        for (int i = 0; i < 16; ++i) s += d_partial[(b * 16 + i) * TGTc + k];
        out[t] = s;
    }
}

// ---------------------------------------------------------------------------
extern "C" void kernel_launch(void* const* d_in, const int* in_sizes, int n_in,
                              void* d_out, int out_size) {
    const float* g    = (const float*)d_in[0];
    const float* h_in = (const float*)d_in[1];
    const int*   e    = (const int*)  d_in[2];
    const float* A    = (const float*)d_in[3];
    const float* Wi   = (const float*)d_in[4];
    const float* Wh   = (const float*)d_in[5];
    const float* bi   = (const float*)d_in[6];
    const float* bh   = (const float*)d_in[7];
    const float* Wg   = (const float*)d_in[8];
    const float* bg   = (const float*)d_in[9];
    const float* Wo   = (const float*)d_in[10];
    const float* bo   = (const float*)d_in[11];
    float* out = (float*)d_out;

    k_pad <<<BN * Hc / 256, 256>>>(h_in);
    k_mask<<<BN / 8, 256>>>(h_in);
    k_pack<<<(int)((size_t)BN * Nc / 256), 256>>>(g, e);

    for (int layer = 0; layer < NLAYERS; ++layer) {
        k_msg   <<<dim3(BN / 32, Lc), 256>>>(A);
        k_gather<<<dim3(Nc / 32, Bc, SPLIT), 256>>>();
        k_gru   <<<BN / 16, 256>>>(Wi, Wh, bi, bh);
    }

    k_readout<<<dim3(16, Bc), 256>>>(Wg, bg, Wo, bo);
    k_final  <<<1, 128>>>(out);
}

// round 5
// speedup vs baseline: 1.4565x; 1.0414x over previous
#include <cuda_runtime.h>
#include <cuda_fp16.h>
#include <math.h>

// Problem constants
#define Bc      8
#define Nc      1024
#define DIN     64
#define Hc      128
#define MSGc    128
#define Lc      5
#define TGTc    12
#define NLAYERS 3
#define BN      (Bc * Nc)          // 8192 nodes total
#define SPLIT   4                  // w-dimension split for gather

// ---------------- scratch (static device globals; no cudaMalloc allowed) ----
__device__ float d_h  [BN * Hc];
__device__ float d_h0 [BN * Hc];
__device__ uint2 d_Mlh[(size_t)BN * Lc * 32]; // fp16 messages: [b][w][l][32 x (4 halfs)]
__device__ float d_aggp[SPLIT][BN * MSGc];    // partial aggregates per w-split
__device__ float d_mask [BN];
__device__ float d_rmask[BN];
__device__ float d_partial[Bc * 16 * TGTc];
__device__ uint2 d_packbuf[(size_t)BN * Nc];  // {g bits, uint2-offset (w*5+e)*32}

// ----------------------- packed f32x2 helpers (Blackwell FFMA2) -------------
__device__ __forceinline__ unsigned long long pk2(float x, float y) {
    unsigned long long r;
    asm("mov.b64 %0, {%1, %2};" : "=l"(r) : "f"(x), "f"(y));
    return r;
}
__device__ __forceinline__ float2 up2(unsigned long long a) {
    float x, y;
    asm("mov.b64 {%0, %1}, %2;" : "=f"(x), "=f"(y) : "l"(a));
    return make_float2(x, y);
}
__device__ __forceinline__ void fma2(unsigned long long& a,
                                     unsigned long long b, unsigned long long c) {
    asm("fma.rn.f32x2 %0, %1, %2, %0;" : "+l"(a) : "l"(b), "l"(c));
}

// ---------------------------------------------------------------- setup ----
__global__ void k_pad(const float* __restrict__ h_in) {
    int idx  = blockIdx.x * blockDim.x + threadIdx.x;
    int d    = idx & 127;
    int node = idx >> 7;
    float v = (d < DIN) ? h_in[node * DIN + d] : 0.f;
    d_h0[idx] = v;
    d_h [idx] = v;
}

__global__ void k_mask(const float* __restrict__ h_in) {
    int warp = threadIdx.x >> 5, lane = threadIdx.x & 31;
    int node = blockIdx.x * 8 + warp;
    float v0 = h_in[node * DIN + lane];
    float v1 = h_in[node * DIN + 32 + lane];
    float sa = fabsf(v0) + fabsf(v1);
    float ss = v0 + v1;
    #pragma unroll
    for (int off = 16; off; off >>= 1) {
        sa += __shfl_xor_sync(0xffffffffu, sa, off);
        ss += __shfl_xor_sync(0xffffffffu, ss, off);
    }
    if (lane == 0) {
        d_mask [node] = (sa > 0.f) ? 1.f : 0.f;
        d_rmask[node] = (ss > 0.f) ? 1.f : 0.f;
    }
}

// Precompute fused coefficient+offset array (reused by all 3 layers).
__global__ void k_pack(const float* __restrict__ g, const int* __restrict__ e) {
    size_t i = (size_t)blockIdx.x * blockDim.x + threadIdx.x;   // over BN*Nc
    int w = (int)(i & (Nc - 1));
    int s = e[i];
    uint2 p;
    p.x = __float_as_uint(g[i]);
    p.y = (unsigned)((w * Lc + s) * 32);     // uint2 units within a batch slab
    d_packbuf[i] = p;
}

// ------------------- K1: Ml[node][l][:] = h@A_l  (fp32 math, fp16 store) ----
// grid (BN/64, L), 256 threads; warp handles 8 rows; FFMA2 inner loop.
__global__ void k_msg(const float* __restrict__ A) {
    __shared__ float sh[64][128];      // 32 KB
    int rt = blockIdx.x, l = blockIdx.y;
    int t = threadIdx.x;
    #pragma unroll
    for (int k = 0; k < 32; ++k) {
        int idx = t + k * 256;         // 8192 elements
        sh[idx >> 7][idx & 127] = d_h[(size_t)rt * 64 * 128 + idx];
    }
    __syncthreads();
    int warp = t >> 5, lane = t & 31, j4 = lane * 4;
    int rbase = warp * 8;

    unsigned long long acc2[8][2];
    #pragma unroll
    for (int r = 0; r < 8; ++r) { acc2[r][0] = 0ull; acc2[r][1] = 0ull; }

    const float* Ab = A + (size_t)l * 128 * 128 + j4;
    for (int d = 0; d < 128; ++d) {
        ulonglong2 ua = *(const ulonglong2*)(Ab + (size_t)d * 128);
        #pragma unroll
        for (int r = 0; r < 8; ++r) {
            float hv = sh[rbase + r][d];
            unsigned long long vv = pk2(hv, hv);
            fma2(acc2[r][0], vv, ua.x);
            fma2(acc2[r][1], vv, ua.y);
        }
    }
    #pragma unroll
    for (int r = 0; r < 8; ++r) {
        int node = rt * 64 + rbase + r;
        float2 a01 = up2(acc2[r][0]);
        float2 a23 = up2(acc2[r][1]);
        __half2 p0 = __float22half2_rn(a01);
        __half2 p1 = __float22half2_rn(a23);
        uint2 o;
        o.x = *(unsigned*)&p0;
        o.y = *(unsigned*)&p1;
        d_Mlh[((size_t)node * Lc + l) * 32 + lane] = o;
    }
}

// ------------------- K2: aggp[sp][b,v,:] = sum_{w in split} g*Ml[e][w,:] ----
// fp16 message rows: LDG.64 per lane (2 wavefronts/edge/warp instead of 4).
__global__ void __launch_bounds__(256)
k_gather() {
    __shared__ uint2 p_sm[32][64];      // 16 KB
    int vt = blockIdx.x, b = blockIdx.y, sp = blockIdx.z;
    int t = threadIdx.x, warp = t >> 5, lane = t & 31, j4 = lane * 4;
    int vbase = vt * 32;

    float4 acc[4];
    #pragma unroll
    for (int r = 0; r < 4; ++r) acc[r] = make_float4(0.f, 0.f, 0.f, 0.f);

    const uint2* Mlb = d_Mlh + (size_t)b * Nc * Lc * 32 + lane;

    for (int wt = sp * 4; wt < sp * 4 + 4; ++wt) {
        int wbase = wt * 64;
        __syncthreads();
        #pragma unroll
        for (int kk = 0; kk < 8; ++kk) {
            int idx = t + kk * 256;
            int r = idx >> 6, w = idx & 63;
            p_sm[r][w] = d_packbuf[((size_t)(b * Nc + vbase + r)) * Nc + wbase + w];
        }
        __syncthreads();

        int r0 = warp * 4;
        #pragma unroll 4
        for (int w = 0; w < 64; ++w) {
            #pragma unroll
            for (int r = 0; r < 4; ++r) {
                uint2 pk = p_sm[r0 + r][w];
                float c = __uint_as_float(pk.x);
                uint2 m = Mlb[pk.y];
                float2 f0 = __half22float2(*reinterpret_cast<const __half2*>(&m.x));
                float2 f1 = __half22float2(*reinterpret_cast<const __half2*>(&m.y));
                acc[r].x += c * f0.x;
                acc[r].y += c * f0.y;
                acc[r].z += c * f1.x;
                acc[r].w += c * f1.y;
            }
        }
    }
    int r0 = warp * 4;
    #pragma unroll
    for (int r = 0; r < 4; ++r) {
        int v = vbase + r0 + r;
        *(float4*)&d_aggp[sp][((size_t)(b * Nc + v)) * MSGc + j4] = acc[r];
    }
}

// -------------------------------------------------- K3: GRU step + mask -----
__device__ __forceinline__ float gru_comp(float irv, float izv, float inv,
                                          float hrv, float hzv, float hnv,
                                          float hold, float m) {
    float r = 1.f / (1.f + expf(-(irv + hrv)));
    float z = 1.f / (1.f + expf(-(izv + hzv)));
    float n = tanhf(inv + r * hnv);
    return ((1.f - z) * n + z * hold) * m;
}

// Warp-pair design + FFMA2: even warp gi = agg@Wi + bi (4 rows), odd warp
// gh = h@Wh + bh (same 4 rows), weights loaded as natural f32x2 pairs.
__global__ void k_gru(const float* __restrict__ Wi, const float* __restrict__ Wh,
                      const float* __restrict__ bi, const float* __restrict__ bh) {
    __shared__ float a_sm[16][128];      // 8 KB
    __shared__ float h_sm[16][128];      // 8 KB
    __shared__ float gh_sm[16][384];     // 24 KB
    int tile = blockIdx.x;               // 512 blocks, 16 rows each
    int t = threadIdx.x, warp = t >> 5, lane = t & 31, j4 = lane * 4;
    int pair = warp >> 1;
    bool isI = (warp & 1) == 0;
    int rbase = pair * 4;

    #pragma unroll
    for (int k = 0; k < 8; ++k) {
        int idx = t + k * 256;
        size_t go = (size_t)tile * 16 * 128 + idx;
        a_sm[idx >> 7][idx & 127] = d_aggp[0][go] + d_aggp[1][go]
                                  + d_aggp[2][go] + d_aggp[3][go];
        h_sm[idx >> 7][idx & 127] = d_h[go];
    }
    __syncthreads();

    const float* W  = isI ? Wi : Wh;
    const float* bb = isI ? bi : bh;
    float (*src)[128] = isI ? a_sm : h_sm;

    unsigned long long acc2[4][3][2];
    #pragma unroll
    for (int gq = 0; gq < 3; ++gq) {
        unsigned long long b0 = pk2(bb[gq * 128 + j4],     bb[gq * 128 + j4 + 1]);
        unsigned long long b1 = pk2(bb[gq * 128 + j4 + 2], bb[gq * 128 + j4 + 3]);
        #pragma unroll
        for (int r = 0; r < 4; ++r) { acc2[r][gq][0] = b0; acc2[r][gq][1] = b1; }
    }

    for (int d = 0; d < 128; ++d) {
        const float* wrow = W + (size_t)d * 384 + j4;
        ulonglong2 u0 = *(const ulonglong2*)(wrow);
        ulonglong2 u1 = *(const ulonglong2*)(wrow + 128);
        ulonglong2 u2 = *(const ulonglong2*)(wrow + 256);
        #pragma unroll
        for (int r = 0; r < 4; ++r) {
            float v = src[rbase + r][d];
            unsigned long long vv = pk2(v, v);
            fma2(acc2[r][0][0], vv, u0.x);
            fma2(acc2[r][0][1], vv, u0.y);
            fma2(acc2[r][1][0], vv, u1.x);
            fma2(acc2[r][1][1], vv, u1.y);
            fma2(acc2[r][2][0], vv, u2.x);
            fma2(acc2[r][2][1], vv, u2.y);
        }
    }

    if (!isI) {
        #pragma unroll
        for (int r = 0; r < 4; ++r)
            #pragma unroll
            for (int gq = 0; gq < 3; ++gq) {
                float2 lo = up2(acc2[r][gq][0]);
                float2 hi = up2(acc2[r][gq][1]);
                *(float4*)&gh_sm[rbase + r][gq * 128 + j4] =
                    make_float4(lo.x, lo.y, hi.x, hi.y);
            }
    }
    __syncthreads();
    if (isI) {
        #pragma unroll
        for (int r = 0; r < 4; ++r) {
            int row = tile * 16 + rbase + r;
            float m = d_mask[row];
            float2 ir01 = up2(acc2[r][0][0]), ir23 = up2(acc2[r][0][1]);
            float2 iz01 = up2(acc2[r][1][0]), iz23 = up2(acc2[r][1][1]);
            float2 in01 = up2(acc2[r][2][0]), in23 = up2(acc2[r][2][1]);
            float4 hr = *(const float4*)&gh_sm[rbase + r][j4];
            float4 hz = *(const float4*)&gh_sm[rbase + r][128 + j4];
            float4 hn = *(const float4*)&gh_sm[rbase + r][256 + j4];
            float4 hold = *(const float4*)&h_sm[rbase + r][j4];
            float4 out;
            out.x = gru_comp(ir01.x, iz01.x, in01.x, hr.x, hz.x, hn.x, hold.x, m);
            out.y = gru_comp(ir01.y, iz01.y, in01.y, hr.y, hz.y, hn.y, hold.y, m);
            out.z = gru_comp(ir23.x, iz23.x, in23.x, hr.z, hz.z, hn.z, hold.z, m);
            out.w = gru_comp(ir23.y, iz23.y, in23.y, hr.w, hz.w, hn.w, hold.w, m);
            *(float4*)&d_h[(size_t)row * 128 + j4] = out;
        }
    }
}

// ------------------------------------------------------------ readout ------
__global__ void k_readout(const float* __restrict__ Wg, const float* __restrict__ bg,
                          const float* __restrict__ Wo, const float* __restrict__ bo) {
    int tile = blockIdx.x, b = blockIdx.y;
    int t = threadIdx.x, lane = t & 31, warp = t >> 5;
    int nl = t >> 2;
    int kg = t & 3;
    int node = b * Nc + tile * 64 + nl;

    float acc_g[3], acc_o[3];
    #pragma unroll
    for (int k3 = 0; k3 < 3; ++k3) {
        int k = kg * 3 + k3;
        acc_g[k3] = bg[k];
        acc_o[k3] = bo[k];
    }
    const float* hT  = d_h  + (size_t)node * 128;
    const float* h0p = d_h0 + (size_t)node * 128;
    for (int d = 0; d < 128; ++d) {
        float ht  = hT[d];
        float h0v = h0p[d];
        #pragma unroll
        for (int k3 = 0; k3 < 3; ++k3) {
            int k = kg * 3 + k3;
            acc_g[k3] += ht * Wg[d * TGTc + k] + h0v * Wg[(128 + d) * TGTc + k];
            acc_o[k3] += ht * Wo[d * TGTc + k];
        }
    }
    float rm = d_rmask[node];
    float vals[3];
    #pragma unroll
    for (int k3 = 0; k3 < 3; ++k3) {
        float gate = 1.f / (1.f + expf(-acc_g[k3]));
        vals[k3] = rm * gate * acc_o[k3];
    }
    #pragma unroll
    for (int off = 16; off >= 4; off >>= 1) {
        #pragma unroll
        for (int k3 = 0; k3 < 3; ++k3)
            vals[k3] += __shfl_xor_sync(0xffffffffu, vals[k3], off);
    }
    __shared__ float red[8][TGTc];
    if (lane < 4) {
        #pragma unroll
        for (int k3 = 0; k3 < 3; ++k3) red[warp][lane * 3 + k3] = vals[k3];
    }
    __syncthreads();
    if (t < TGTc) {
        float s = 0.f;
        #pragma unroll
        for (int wq = 0; wq < 8; ++wq) s += red[wq][t];
        d_partial[(b * 16 + tile) * TGTc + t] = s;
    }
}

__global__ void k_final(float* __restrict__ out) {
    int t = threadIdx.x;
    if (t < Bc * TGTc) {
        int b = t / TGTc, k = t % TGTc;
        float s = 0.f;
        #pragma unroll
        for (int i = 0; i < 16; ++i) s += d_partial[(b * 16 + i) * TGTc + k];
        out[t] = s;
    }
}

// ---------------------------------------------------------------------------
extern "C" void kernel_launch(void* const* d_in, const int* in_sizes, int n_in,
                              void* d_out, int out_size) {
    const float* g    = (const float*)d_in[0];
    const float* h_in = (const float*)d_in[1];
    const int*   e    = (const int*)  d_in[2];
    const float* A    = (const float*)d_in[3];
    const float* Wi   = (const float*)d_in[4];
    const float* Wh   = (const float*)d_in[5];
    const float* bi   = (const float*)d_in[6];
    const float* bh   = (const float*)d_in[7];
    const float* Wg   = (const float*)d_in[8];
    const float* bg   = (const float*)d_in[9];
    const float* Wo   = (const float*)d_in[10];
    const float* bo   = (const float*)d_in[11];
    float* out = (float*)d_out;

    k_pad <<<BN * Hc / 256, 256>>>(h_in);
    k_mask<<<BN / 8, 256>>>(h_in);
    k_pack<<<(int)((size_t)BN * Nc / 256), 256>>>(g, e);

    for (int layer = 0; layer < NLAYERS; ++layer) {
        k_msg   <<<dim3(BN / 64, Lc), 256>>>(A);
        k_gather<<<dim3(Nc / 32, Bc, SPLIT), 256>>>();
        k_gru   <<<BN / 16, 256>>>(Wi, Wh, bi, bh);
    }

    k_readout<<<dim3(16, Bc), 256>>>(Wg, bg, Wo, bo);
    k_final  <<<1, 128>>>(out);
}

// round 6
// speedup vs baseline: 1.4600x; 1.0024x over previous
#include <cuda_runtime.h>
#include <cuda_fp16.h>
#include <math.h>

// Problem constants
#define Bc      8
#define Nc      1024
#define DIN     64
#define Hc      128
#define MSGc    128
#define Lc      5
#define TGTc    12
#define NLAYERS 3
#define BN      (Bc * Nc)          // 8192 nodes total
#define SPLIT   4                  // w-dimension split for gather

// ---------------- scratch (static device globals; no cudaMalloc allowed) ----
__device__ float d_h  [BN * Hc];
__device__ float d_h0 [BN * Hc];
__device__ uint2 d_Mlh[(size_t)BN * Lc * 32]; // fp16 messages: [b][w][l][32 x (4 halfs)]
__device__ float d_aggp[SPLIT][BN * MSGc];    // partial aggregates per w-split
__device__ float d_mask [BN];
__device__ float d_rmask[BN];
__device__ float d_partial[Bc * 16 * TGTc];
__device__ uint2 d_packbuf[(size_t)BN * Nc];  // {g bits, uint2-offset (w*5+e)*32}

// ----------------------- packed f32x2 helpers (Blackwell FFMA2) -------------
__device__ __forceinline__ unsigned long long pk2(float x, float y) {
    unsigned long long r;
    asm("mov.b64 %0, {%1, %2};" : "=l"(r) : "f"(x), "f"(y));
    return r;
}
__device__ __forceinline__ float2 up2(unsigned long long a) {
    float x, y;
    asm("mov.b64 {%0, %1}, %2;" : "=f"(x), "=f"(y) : "l"(a));
    return make_float2(x, y);
}
__device__ __forceinline__ void fma2(unsigned long long& a,
                                     unsigned long long b, unsigned long long c) {
    asm("fma.rn.f32x2 %0, %1, %2, %0;" : "+l"(a) : "l"(b), "l"(c));
}

// ---------------------------------------------------------------- setup ----
__global__ void k_pad(const float* __restrict__ h_in) {
    int idx  = blockIdx.x * blockDim.x + threadIdx.x;
    int d    = idx & 127;
    int node = idx >> 7;
    float v = (d < DIN) ? h_in[node * DIN + d] : 0.f;
    d_h0[idx] = v;
    d_h [idx] = v;
}

__global__ void k_mask(const float* __restrict__ h_in) {
    int warp = threadIdx.x >> 5, lane = threadIdx.x & 31;
    int node = blockIdx.x * 8 + warp;
    float v0 = h_in[node * DIN + lane];
    float v1 = h_in[node * DIN + 32 + lane];
    float sa = fabsf(v0) + fabsf(v1);
    float ss = v0 + v1;
    #pragma unroll
    for (int off = 16; off; off >>= 1) {
        sa += __shfl_xor_sync(0xffffffffu, sa, off);
        ss += __shfl_xor_sync(0xffffffffu, ss, off);
    }
    if (lane == 0) {
        d_mask [node] = (sa > 0.f) ? 1.f : 0.f;
        d_rmask[node] = (ss > 0.f) ? 1.f : 0.f;
    }
}

// Precompute fused coefficient+offset array (reused by all 3 layers).
__global__ void k_pack(const float* __restrict__ g, const int* __restrict__ e) {
    size_t i = (size_t)blockIdx.x * blockDim.x + threadIdx.x;   // over BN*Nc
    int w = (int)(i & (Nc - 1));
    int s = e[i];
    uint2 p;
    p.x = __float_as_uint(g[i]);
    p.y = (unsigned)((w * Lc + s) * 32);     // uint2 units within a batch slab
    d_packbuf[i] = p;
}

// ------------------- K1: Ml[node][l][:] = h@A_l  (fp32 math, fp16 store) ----
// grid (BN/64, L), 256 threads; warp handles 8 rows; FFMA2 inner loop.
__global__ void k_msg(const float* __restrict__ A) {
    __shared__ float sh[64][128];      // 32 KB
    int rt = blockIdx.x, l = blockIdx.y;
    int t = threadIdx.x;
    #pragma unroll
    for (int k = 0; k < 32; ++k) {
        int idx = t + k * 256;         // 8192 elements
        sh[idx >> 7][idx & 127] = d_h[(size_t)rt * 64 * 128 + idx];
    }
    __syncthreads();
    int warp = t >> 5, lane = t & 31, j4 = lane * 4;
    int rbase = warp * 8;

    unsigned long long acc2[8][2];
    #pragma unroll
    for (int r = 0; r < 8; ++r) { acc2[r][0] = 0ull; acc2[r][1] = 0ull; }

    const float* Ab = A + (size_t)l * 128 * 128 + j4;
    for (int d = 0; d < 128; ++d) {
        ulonglong2 ua = *(const ulonglong2*)(Ab + (size_t)d * 128);
        #pragma unroll
        for (int r = 0; r < 8; ++r) {
            float hv = sh[rbase + r][d];
            unsigned long long vv = pk2(hv, hv);
            fma2(acc2[r][0], vv, ua.x);
            fma2(acc2[r][1], vv, ua.y);
        }
    }
    #pragma unroll
    for (int r = 0; r < 8; ++r) {
        int node = rt * 64 + rbase + r;
        float2 a01 = up2(acc2[r][0]);
        float2 a23 = up2(acc2[r][1]);
        __half2 p0 = __float22half2_rn(a01);
        __half2 p1 = __float22half2_rn(a23);
        uint2 o;
        o.x = *(unsigned*)&p0;
        o.y = *(unsigned*)&p1;
        d_Mlh[((size_t)node * Lc + l) * 32 + lane] = o;
    }
}

// ------------------- K2: aggp[sp][b,v,:] = sum_{w in split} g*Ml[e][w,:] ----
// fp16 message rows: LDG.64 per lane (2 wavefronts/edge/warp instead of 4).
__global__ void __launch_bounds__(256)
k_gather() {
    __shared__ uint2 p_sm[32][64];      // 16 KB
    int vt = blockIdx.x, b = blockIdx.y, sp = blockIdx.z;
    int t = threadIdx.x, warp = t >> 5, lane = t & 31, j4 = lane * 4;
    int vbase = vt * 32;

    float4 acc[4];
    #pragma unroll
    for (int r = 0; r < 4; ++r) acc[r] = make_float4(0.f, 0.f, 0.f, 0.f);

    const uint2* Mlb = d_Mlh + (size_t)b * Nc * Lc * 32 + lane;

    for (int wt = sp * 4; wt < sp * 4 + 4; ++wt) {
        int wbase = wt * 64;
        __syncthreads();
        #pragma unroll
        for (int kk = 0; kk < 8; ++kk) {
            int idx = t + kk * 256;
            int r = idx >> 6, w = idx & 63;
            p_sm[r][w] = d_packbuf[((size_t)(b * Nc + vbase + r)) * Nc + wbase + w];
        }
        __syncthreads();

        int r0 = warp * 4;
        #pragma unroll 4
        for (int w = 0; w < 64; ++w) {
            #pragma unroll
            for (int r = 0; r < 4; ++r) {
                uint2 pk = p_sm[r0 + r][w];
                float c = __uint_as_float(pk.x);
                uint2 m = Mlb[pk.y];
                float2 f0 = __half22float2(*reinterpret_cast<const __half2*>(&m.x));
                float2 f1 = __half22float2(*reinterpret_cast<const __half2*>(&m.y));
                acc[r].x += c * f0.x;
                acc[r].y += c * f0.y;
                acc[r].z += c * f1.x;
                acc[r].w += c * f1.y;
            }
        }
    }
    int r0 = warp * 4;
    #pragma unroll
    for (int r = 0; r < 4; ++r) {
        int v = vbase + r0 + r;
        *(float4*)&d_aggp[sp][((size_t)(b * Nc + v)) * MSGc + j4] = acc[r];
    }
}

// -------------------------------------------------- K3: GRU step + mask -----
__device__ __forceinline__ float gru_comp(float irv, float izv, float inv,
                                          float hrv, float hzv, float hnv,
                                          float hold, float m) {
    float r = 1.f / (1.f + expf(-(irv + hrv)));
    float z = 1.f / (1.f + expf(-(izv + hzv)));
    float n = tanhf(inv + r * hnv);
    return ((1.f - z) * n + z * hold) * m;
}

// Warp-pair design + FFMA2: even warp gi = agg@Wi + bi (4 rows), odd warp
// gh = h@Wh + bh (same 4 rows), weights loaded as natural f32x2 pairs.
__global__ void k_gru(const float* __restrict__ Wi, const float* __restrict__ Wh,
                      const float* __restrict__ bi, const float* __restrict__ bh) {
    __shared__ float a_sm[16][128];      // 8 KB
    __shared__ float h_sm[16][128];      // 8 KB
    __shared__ float gh_sm[16][384];     // 24 KB
    int tile = blockIdx.x;               // 512 blocks, 16 rows each
    int t = threadIdx.x, warp = t >> 5, lane = t & 31, j4 = lane * 4;
    int pair = warp >> 1;
    bool isI = (warp & 1) == 0;
    int rbase = pair * 4;

    #pragma unroll
    for (int k = 0; k < 8; ++k) {
        int idx = t + k * 256;
        size_t go = (size_t)tile * 16 * 128 + idx;
        a_sm[idx >> 7][idx & 127] = d_aggp[0][go] + d_aggp[1][go]
                                  + d_aggp[2][go] + d_aggp[3][go];
        h_sm[idx >> 7][idx & 127] = d_h[go];
    }
    __syncthreads();

    const float* W  = isI ? Wi : Wh;
    const float* bb = isI ? bi : bh;
    float (*src)[128] = isI ? a_sm : h_sm;

    unsigned long long acc2[4][3][2];
    #pragma unroll
    for (int gq = 0; gq < 3; ++gq) {
        unsigned long long b0 = pk2(bb[gq * 128 + j4],     bb[gq * 128 + j4 + 1]);
        unsigned long long b1 = pk2(bb[gq * 128 + j4 + 2], bb[gq * 128 + j4 + 3]);
        #pragma unroll
        for (int r = 0; r < 4; ++r) { acc2[r][gq][0] = b0; acc2[r][gq][1] = b1; }
    }

    for (int d = 0; d < 128; ++d) {
        const float* wrow = W + (size_t)d * 384 + j4;
        ulonglong2 u0 = *(const ulonglong2*)(wrow);
        ulonglong2 u1 = *(const ulonglong2*)(wrow + 128);
        ulonglong2 u2 = *(const ulonglong2*)(wrow + 256);
        #pragma unroll
        for (int r = 0; r < 4; ++r) {
            float v = src[rbase + r][d];
            unsigned long long vv = pk2(v, v);
            fma2(acc2[r][0][0], vv, u0.x);
            fma2(acc2[r][0][1], vv, u0.y);
            fma2(acc2[r][1][0], vv, u1.x);
            fma2(acc2[r][1][1], vv, u1.y);
            fma2(acc2[r][2][0], vv, u2.x);
            fma2(acc2[r][2][1], vv, u2.y);
        }
    }

    if (!isI) {
        #pragma unroll
        for (int r = 0; r < 4; ++r)
            #pragma unroll
            for (int gq = 0; gq < 3; ++gq) {
                float2 lo = up2(acc2[r][gq][0]);
                float2 hi = up2(acc2[r][gq][1]);
                *(float4*)&gh_sm[rbase + r][gq * 128 + j4] =
                    make_float4(lo.x, lo.y, hi.x, hi.y);
            }
    }
    __syncthreads();
    if (isI) {
        #pragma unroll
        for (int r = 0; r < 4; ++r) {
            int row = tile * 16 + rbase + r;
            float m = d_mask[row];
            float2 ir01 = up2(acc2[r][0][0]), ir23 = up2(acc2[r][0][1]);
            float2 iz01 = up2(acc2[r][1][0]), iz23 = up2(acc2[r][1][1]);
            float2 in01 = up2(acc2[r][2][0]), in23 = up2(acc2[r][2][1]);
            float4 hr = *(const float4*)&gh_sm[rbase + r][j4];
            float4 hz = *(const float4*)&gh_sm[rbase + r][128 + j4];
            float4 hn = *(const float4*)&gh_sm[rbase + r][256 + j4];
            float4 hold = *(const float4*)&h_sm[rbase + r][j4];
            float4 out;
            out.x = gru_comp(ir01.x, iz01.x, in01.x, hr.x, hz.x, hn.x, hold.x, m);
            out.y = gru_comp(ir01.y, iz01.y, in01.y, hr.y, hz.y, hn.y, hold.y, m);
            out.z = gru_comp(ir23.x, iz23.x, in23.x, hr.z, hz.z, hn.z, hold.z, m);
            out.w = gru_comp(ir23.y, iz23.y, in23.y, hr.w, hz.w, hn.w, hold.w, m);
            *(float4*)&d_h[(size_t)row * 128 + j4] = out;
        }
    }
}

// ------------------------------------------------------------ readout ------
__global__ void k_readout(const float* __restrict__ Wg, const float* __restrict__ bg,
                          const float* __restrict__ Wo, const float* __restrict__ bo) {
    int tile = blockIdx.x, b = blockIdx.y;
    int t = threadIdx.x, lane = t & 31, warp = t >> 5;
    int nl = t >> 2;
    int kg = t & 3;
    int node = b * Nc + tile * 64 + nl;

    float acc_g[3], acc_o[3];
    #pragma unroll
    for (int k3 = 0; k3 < 3; ++k3) {
        int k = kg * 3 + k3;
        acc_g[k3] = bg[k];
        acc_o[k3] = bo[k];
    }
    const float* hT  = d_h  + (size_t)node * 128;
    const float* h0p = d_h0 + (size_t)node * 128;
    for (int d = 0; d < 128; ++d) {
        float ht  = hT[d];
        float h0v = h0p[d];
        #pragma unroll
        for (int k3 = 0; k3 < 3; ++k3) {
            int k = kg * 3 + k3;
            acc_g[k3] += ht * Wg[d * TGTc + k] + h0v * Wg[(128 + d) * TGTc + k];
            acc_o[k3] += ht * Wo[d * TGTc + k];
        }
    }
    float rm = d_rmask[node];
    float vals[3];
    #pragma unroll
    for (int k3 = 0; k3 < 3; ++k3) {
        float gate = 1.f / (1.f + expf(-acc_g[k3]));
        vals[k3] = rm * gate * acc_o[k3];
    }
    #pragma unroll
    for (int off = 16; off >= 4; off >>= 1) {
        #pragma unroll
        for (int k3 = 0; k3 < 3; ++k3)
            vals[k3] += __shfl_xor_sync(0xffffffffu, vals[k3], off);
    }
    __shared__ float red[8][TGTc];
    if (lane < 4) {
        #pragma unroll
        for (int k3 = 0; k3 < 3; ++k3) red[warp][lane * 3 + k3] = vals[k3];
    }
    __syncthreads();
    if (t < TGTc) {
        float s = 0.f;
        #pragma unroll
        for (int wq = 0; wq < 8; ++wq) s += red[wq][t];
        d_partial[(b * 16 + tile) * TGTc + t] = s;
    }
}

__global__ void k_final(float* __restrict__ out) {
    int t = threadIdx.x;
    if (t < Bc * TGTc) {
        int b = t / TGTc, k = t % TGTc;
        float s = 0.f;
        #pragma unroll
        for (int i = 0; i < 16; ++i) s += d_partial[(b * 16 + i) * TGTc + k];
        out[t] = s;
    }
}

// ---------------------------------------------------------------------------
extern "C" void kernel_launch(void* const* d_in, const int* in_sizes, int n_in,
                              void* d_out, int out_size) {
    const float* g    = (const float*)d_in[0];
    const float* h_in = (const float*)d_in[1];
    const int*   e    = (const int*)  d_in[2];
    const float* A    = (const float*)d_in[3];
    const float* Wi   = (const float*)d_in[4];
    const float* Wh   = (const float*)d_in[5];
    const float* bi   = (const float*)d_in[6];
    const float* bh   = (const float*)d_in[7];
    const float* Wg   = (const float*)d_in[8];
    const float* bg   = (const float*)d_in[9];
    const float* Wo   = (const float*)d_in[10];
    const float* bo   = (const float*)d_in[11];
    float* out = (float*)d_out;

    k_pad <<<BN * Hc / 256, 256>>>(h_in);
    k_mask<<<BN / 8, 256>>>(h_in);
    k_pack<<<(int)((size_t)BN * Nc / 256), 256>>>(g, e);

    for (int layer = 0; layer < NLAYERS; ++layer) {
        k_msg   <<<dim3(BN / 64, Lc), 256>>>(A);
        k_gather<<<dim3(Nc / 32, Bc, SPLIT), 256>>>();
        k_gru   <<<BN / 16, 256>>>(Wi, Wh, bi, bh);
    }

    k_readout<<<dim3(16, Bc), 256>>>(Wg, bg, Wo, bo);
    k_final  <<<1, 128>>>(out);
}